// round 1
// baseline (speedup 1.0000x reference)
#include <cuda_runtime.h>

#define NC_ 4096
#define NP_ 4096
#define DD  1024

// Scratch: 6 projection buffers (100 MB) + 2 score matrices (128 MB).
__device__ float g_proj[6][(size_t)NC_ * DD];
__device__ float g_score[2][(size_t)NC_ * NP_];

// ---------------------------------------------------------------------------
// 128x128x16 register-blocked SGEMM.
//   BT = true : C[M,N] = A[M,K] * B[N,K]^T (+bias)     (A,B both K-major)
//   BT = false: C[M,N] = A[M,K] * B[K,N]   (+bias)     (B N-major)
// 256 threads, 8x8 per-thread tile.
// ---------------------------------------------------------------------------
template <bool BT>
__global__ __launch_bounds__(256, 2)
void gemm128(const float* __restrict__ A, const float* __restrict__ B,
             const float* __restrict__ bias, float* __restrict__ C,
             int M, int N, int K) {
    __shared__ float As[16][132];
    __shared__ float Bs[16][132];

    const int bx = blockIdx.x, by = blockIdx.y;
    const int tid = threadIdx.x;
    const int tx = tid & 15;       // 0..15 -> output cols tx*8..tx*8+7
    const int ty = tid >> 4;       // 0..15 -> output rows ty*8..ty*8+7

    float acc[8][8] = {};

    const float* Ab = A + (size_t)(by * 128) * K;

    for (int kt = 0; kt < K; kt += 16) {
        // Load A tile [128 rows x 16 k], transpose into As[k][m]
#pragma unroll
        for (int l = 0; l < 2; l++) {
            int idx = tid + l * 256;          // 0..511
            int row = idx >> 2;               // 0..127
            int kq  = (idx & 3) << 2;         // 0,4,8,12
            const float4 a = *(const float4*)(Ab + (size_t)row * K + kt + kq);
            As[kq + 0][row] = a.x;
            As[kq + 1][row] = a.y;
            As[kq + 2][row] = a.z;
            As[kq + 3][row] = a.w;
        }
        if (BT) {
            const float* Bb = B + (size_t)(bx * 128) * K;
#pragma unroll
            for (int l = 0; l < 2; l++) {
                int idx = tid + l * 256;
                int row = idx >> 2;
                int kq  = (idx & 3) << 2;
                const float4 b = *(const float4*)(Bb + (size_t)row * K + kt + kq);
                Bs[kq + 0][row] = b.x;
                Bs[kq + 1][row] = b.y;
                Bs[kq + 2][row] = b.z;
                Bs[kq + 3][row] = b.w;
            }
        } else {
#pragma unroll
            for (int l = 0; l < 2; l++) {
                int idx  = tid + l * 256;
                int krow = idx >> 5;           // 0..15
                int nq   = (idx & 31) << 2;    // 0..124
                *(float4*)&Bs[krow][nq] =
                    *(const float4*)(B + (size_t)(kt + krow) * N + bx * 128 + nq);
            }
        }
        __syncthreads();

#pragma unroll
        for (int k = 0; k < 16; k++) {
            float a[8], b[8];
            *(float4*)&a[0] = *(const float4*)&As[k][ty * 8];
            *(float4*)&a[4] = *(const float4*)&As[k][ty * 8 + 4];
            *(float4*)&b[0] = *(const float4*)&Bs[k][tx * 8];
            *(float4*)&b[4] = *(const float4*)&Bs[k][tx * 8 + 4];
#pragma unroll
            for (int i = 0; i < 8; i++)
#pragma unroll
                for (int j = 0; j < 8; j++)
                    acc[i][j] = fmaf(a[i], b[j], acc[i][j]);
        }
        __syncthreads();
    }

#pragma unroll
    for (int i = 0; i < 8; i++) {
        const int row = by * 128 + ty * 8 + i;
        float* Crow = C + (size_t)row * N + bx * 128 + tx * 8;
#pragma unroll
        for (int j = 0; j < 8; j += 4) {
            float4 v;
            v.x = acc[i][j + 0];
            v.y = acc[i][j + 1];
            v.z = acc[i][j + 2];
            v.w = acc[i][j + 3];
            if (bias) {
                const int col = bx * 128 + tx * 8 + j;
                v.x += bias[col + 0];
                v.y += bias[col + 1];
                v.z += bias[col + 2];
                v.w += bias[col + 3];
            }
            *(float4*)(Crow + j) = v;
        }
    }
}

// ---------------------------------------------------------------------------
// In-place row softmax over 4096 columns (scale 1/32 folded in).
// One block (256 threads) per row; 16 elements per thread kept in registers.
// ---------------------------------------------------------------------------
__global__ __launch_bounds__(256)
void softmax4096(float* __restrict__ S) {
    const int   row = blockIdx.x;
    float*      p   = S + (size_t)row * 4096;
    const int   tid = threadIdx.x;
    const float isc = 0.03125f;  // 1/sqrt(1024)

    __shared__ float shm[8];
    __shared__ float shs[8];

    float buf[16];
    float m = -1e30f;
#pragma unroll
    for (int i = 0; i < 4; i++) {
        float4 t = ((const float4*)p)[i * 256 + tid];
        buf[i * 4 + 0] = t.x * isc;
        buf[i * 4 + 1] = t.y * isc;
        buf[i * 4 + 2] = t.z * isc;
        buf[i * 4 + 3] = t.w * isc;
        m = fmaxf(m, fmaxf(fmaxf(buf[i * 4 + 0], buf[i * 4 + 1]),
                           fmaxf(buf[i * 4 + 2], buf[i * 4 + 3])));
    }
    // block max
#pragma unroll
    for (int o = 16; o; o >>= 1) m = fmaxf(m, __shfl_xor_sync(0xffffffffu, m, o));
    if ((tid & 31) == 0) shm[tid >> 5] = m;
    __syncthreads();
    if (tid == 0) {
        float mm = shm[0];
#pragma unroll
        for (int w = 1; w < 8; w++) mm = fmaxf(mm, shm[w]);
        shm[0] = mm;
    }
    __syncthreads();
    m = shm[0];

    float s = 0.f;
#pragma unroll
    for (int i = 0; i < 16; i++) {
        float e = __expf(buf[i] - m);
        buf[i] = e;
        s += e;
    }
#pragma unroll
    for (int o = 16; o; o >>= 1) s += __shfl_xor_sync(0xffffffffu, s, o);
    if ((tid & 31) == 0) shs[tid >> 5] = s;
    __syncthreads();
    if (tid == 0) {
        float ss = shs[0];
#pragma unroll
        for (int w = 1; w < 8; w++) ss += shs[w];
        shs[0] = ss;
    }
    __syncthreads();
    const float r = 1.f / shs[0];

#pragma unroll
    for (int i = 0; i < 4; i++) {
        float4 t;
        t.x = buf[i * 4 + 0] * r;
        t.y = buf[i * 4 + 1] * r;
        t.z = buf[i * 4 + 2] * r;
        t.w = buf[i * 4 + 3] * r;
        ((float4*)p)[i * 256 + tid] = t;
    }
}

// ---------------------------------------------------------------------------
extern "C" void kernel_launch(void* const* d_in, const int* in_sizes, int n_in,
                              void* d_out, int out_size) {
    const float* X[6];
    for (int i = 0; i < 6; i++) X[i] = (const float*)d_in[i];

    // Weights/biases: tolerate both metadata orderings.
    //   interleaved: W0,b0,W1,b1,...   (setup_inputs dict order)
    //   grouped:     W0..W5, b0..b5    (reference signature order)
    const float *W[6], *Bv[6];
    if (n_in >= 8 && in_sizes[7] == DD) {
        for (int i = 0; i < 6; i++) {
            W[i]  = (const float*)d_in[6 + 2 * i];
            Bv[i] = (const float*)d_in[7 + 2 * i];
        }
    } else {
        for (int i = 0; i < 6; i++) {
            W[i]  = (const float*)d_in[6 + i];
            Bv[i] = (const float*)d_in[12 + i];
        }
    }

    float* proj;
    float* score;
    cudaGetSymbolAddress((void**)&proj, g_proj);
    cudaGetSymbolAddress((void**)&score, g_score);

    float* P[6];
    for (int i = 0; i < 6; i++) P[i] = proj + (size_t)i * NC_ * DD;
    float* S1 = score;                        // [NC, NP]  qc @ kp^T
    float* S2 = score + (size_t)NC_ * NP_;    // [NP, NC]  qp @ kc^T

    dim3 blk(256);
    dim3 gp(DD / 128, NC_ / 128);   // projection & PV output grids
    dim3 gs(NP_ / 128, NC_ / 128);  // score grids

    // Projections: P[i] = X[i] @ W[i]^T + b[i]
    for (int i = 0; i < 6; i++)
        gemm128<true><<<gp, blk>>>(X[i], W[i], Bv[i], P[i], NC_, DD, DD);

    // Scores
    gemm128<true><<<gs, blk>>>(P[0], P[4], nullptr, S1, NC_, NP_, DD);  // qc@kp^T
    gemm128<true><<<gs, blk>>>(P[3], P[1], nullptr, S2, NP_, NC_, DD);  // qp@kc^T

    softmax4096<<<NC_, 256>>>(S1);
    softmax4096<<<NP_, 256>>>(S2);

    float* out = (float*)d_out;
    // comp_fused = S1 @ vp ; prot_fused = S2 @ vc
    gemm128<false><<<gp, blk>>>(S1, P[5], nullptr, out, NC_, DD, NP_);
    gemm128<false><<<gp, blk>>>(S2, P[2], nullptr, out + (size_t)NC_ * DD, NP_, DD, NC_);
}

// round 3
// speedup vs baseline: 2.9703x; 2.9703x over previous
#include <cuda_runtime.h>
#include <cstdint>

#define NC_ 4096
#define NP_ 4096
#define DD  1024

#define BK      32
#define LDA     36                    // padded row stride (floats)
#define STAGES  3
#define STAGE_FLOATS (256 * LDA)      // 128 A-rows + 128 B-rows, 36 floats each
#define GEMM_SMEM (STAGES * STAGE_FLOATS * 4)

// Scratch: 6 projection buffers (100 MB) + 2 score matrices (128 MB).
__device__ float g_proj[6][(size_t)NC_ * DD];
__device__ float g_score[2][(size_t)NC_ * NP_];

// ---------------------------------------------------------------------------
__device__ __forceinline__ void cp16(void* dst, const void* src) {
    uint32_t a;
    asm("{ .reg .u64 t; cvta.to.shared.u64 t, %1; cvt.u32.u64 %0, t; }"
        : "=r"(a) : "l"(dst));
    asm volatile("cp.async.cg.shared.global [%0], [%1], 16;" :: "r"(a), "l"(src));
}

__device__ __forceinline__ uint32_t f2t(float x) {
    uint32_t r;
    asm("cvt.rna.tf32.f32 %0, %1;" : "=r"(r) : "f"(x));
    return r;
}

__device__ __forceinline__ void mma_tf32(float* d, const uint32_t* a, const uint32_t* b) {
    asm volatile(
        "mma.sync.aligned.m16n8k8.row.col.f32.tf32.tf32.f32 "
        "{%0,%1,%2,%3}, {%4,%5,%6,%7}, {%8,%9}, {%0,%1,%2,%3};"
        : "+f"(d[0]), "+f"(d[1]), "+f"(d[2]), "+f"(d[3])
        : "r"(a[0]), "r"(a[1]), "r"(a[2]), "r"(a[3]), "r"(b[0]), "r"(b[1]));
}

// ---------------------------------------------------------------------------
// tf32 mma.sync NT GEMM: C[M,N] = A[M,K] * B[N,K]^T (+bias)
//   biasMode: 0=none, 1=bias[n] (per column), 2=bias[m] (per row)
// 256 threads, 8 warps (2M x 4N), warp tile 64x32, CTA tile 128x128x32.
// ---------------------------------------------------------------------------
__global__ __launch_bounds__(256)
void gemm_mma(const float* __restrict__ A, const float* __restrict__ B,
              const float* __restrict__ bias, float* __restrict__ C,
              int M, int N, int K, int biasMode) {
    extern __shared__ float sm[];
    const int tid = threadIdx.x;
    const int wid = tid >> 5;
    const int lane = tid & 31;
    const int bx = blockIdx.x, by = blockIdx.y;
    const int T = K / BK;

    const float* gA = A + (size_t)(by * 128) * K;
    const float* gB = B + (size_t)(bx * 128) * K;

    auto load_tile = [&](int stage, int kt) {
        float* sA = sm + stage * STAGE_FLOATS;
        float* sB = sA + 128 * LDA;
        const float* pA = gA + kt * BK;
        const float* pB = gB + kt * BK;
#pragma unroll
        for (int l = 0; l < 4; l++) {
            const int idx = l * 256 + tid;   // 0..1023
            const int row = idx >> 3;        // 0..127
            const int q = idx & 7;           // float4 index within 32-float row
            cp16(sA + row * LDA + q * 4, pA + (size_t)row * K + q * 4);
            cp16(sB + row * LDA + q * 4, pB + (size_t)row * K + q * 4);
        }
        asm volatile("cp.async.commit_group;" ::: "memory");
    };

    // prologue: stages 0,1
    load_tile(0, 0);
    load_tile(1, 1);

    const int wm = wid & 1;   // 0..1
    const int wn = wid >> 1;  // 0..3
    const int r = lane >> 2;  // 0..7
    const int c = lane & 3;   // 0..3

    float acc[4][4][4] = {};

    for (int kt = 0; kt < T; kt++) {
        if (kt < T - 1)
            asm volatile("cp.async.wait_group 1;" ::: "memory");
        else
            asm volatile("cp.async.wait_group 0;" ::: "memory");
        __syncthreads();

        const int stage = kt % STAGES;
        const float* sA = sm + stage * STAGE_FLOATS + (wm * 64 + r) * LDA + c;
        const float* sB = sm + stage * STAGE_FLOATS + 128 * LDA + (wn * 32 + r) * LDA + c;

#pragma unroll
        for (int kk = 0; kk < 4; kk++) {
            const int k0 = kk * 8;
            uint32_t a[4][4];
#pragma unroll
            for (int mi = 0; mi < 4; mi++) {
                const float* p = sA + mi * 16 * LDA + k0;
                a[mi][0] = f2t(p[0]);
                a[mi][1] = f2t(p[8 * LDA]);
                a[mi][2] = f2t(p[4]);
                a[mi][3] = f2t(p[8 * LDA + 4]);
            }
            uint32_t b[4][2];
#pragma unroll
            for (int nj = 0; nj < 4; nj++) {
                const float* p = sB + nj * 8 * LDA + k0;
                b[nj][0] = f2t(p[0]);
                b[nj][1] = f2t(p[4]);
            }
#pragma unroll
            for (int mi = 0; mi < 4; mi++)
#pragma unroll
                for (int nj = 0; nj < 4; nj++)
                    mma_tf32(acc[mi][nj], a[mi], b[nj]);
        }
        __syncthreads();

        if (kt + 2 < T) load_tile((kt + 2) % STAGES, kt + 2);
    }

    // ---------------- epilogue ----------------
#pragma unroll
    for (int mi = 0; mi < 4; mi++) {
#pragma unroll
        for (int nj = 0; nj < 4; nj++) {
            const int row0 = by * 128 + wm * 64 + mi * 16 + r;
            const int col = bx * 128 + wn * 32 + nj * 8 + c * 2;
            float2 v0 = make_float2(acc[mi][nj][0], acc[mi][nj][1]);
            float2 v1 = make_float2(acc[mi][nj][2], acc[mi][nj][3]);
            if (biasMode == 1) {
                const float b0 = bias[col], b1 = bias[col + 1];
                v0.x += b0; v0.y += b1;
                v1.x += b0; v1.y += b1;
            } else if (biasMode == 2) {
                const float rb0 = bias[row0];
                const float rb1 = bias[row0 + 8];
                v0.x += rb0; v0.y += rb0;
                v1.x += rb1; v1.y += rb1;
            }
            *(float2*)(C + (size_t)row0 * N + col) = v0;
            *(float2*)(C + (size_t)(row0 + 8) * N + col) = v1;
        }
    }
}

// ---------------------------------------------------------------------------
// In-place row softmax over 4096 columns (scale 1/32 folded in).
// ---------------------------------------------------------------------------
__global__ __launch_bounds__(256)
void softmax4096(float* __restrict__ S) {
    const int row = blockIdx.x;
    float* p = S + (size_t)row * 4096;
    const int tid = threadIdx.x;
    const float isc = 0.03125f;  // 1/sqrt(1024)

    __shared__ float shm[8];
    __shared__ float shs[8];

    float buf[16];
    float m = -1e30f;
#pragma unroll
    for (int i = 0; i < 4; i++) {
        float4 t = ((const float4*)p)[i * 256 + tid];
        buf[i * 4 + 0] = t.x * isc;
        buf[i * 4 + 1] = t.y * isc;
        buf[i * 4 + 2] = t.z * isc;
        buf[i * 4 + 3] = t.w * isc;
        m = fmaxf(m, fmaxf(fmaxf(buf[i * 4], buf[i * 4 + 1]),
                           fmaxf(buf[i * 4 + 2], buf[i * 4 + 3])));
    }
#pragma unroll
    for (int o = 16; o; o >>= 1) m = fmaxf(m, __shfl_xor_sync(0xffffffffu, m, o));
    if ((tid & 31) == 0) shm[tid >> 5] = m;
    __syncthreads();
    if (tid == 0) {
        float mm = shm[0];
#pragma unroll
        for (int w = 1; w < 8; w++) mm = fmaxf(mm, shm[w]);
        shm[0] = mm;
    }
    __syncthreads();
    m = shm[0];

    float s = 0.f;
#pragma unroll
    for (int i = 0; i < 16; i++) {
        float e = __expf(buf[i] - m);
        buf[i] = e;
        s += e;
    }
#pragma unroll
    for (int o = 16; o; o >>= 1) s += __shfl_xor_sync(0xffffffffu, s, o);
    if ((tid & 31) == 0) shs[tid >> 5] = s;
    __syncthreads();
    if (tid == 0) {
        float ss = shs[0];
#pragma unroll
        for (int w = 1; w < 8; w++) ss += shs[w];
        shs[0] = ss;
    }
    __syncthreads();
    const float r = 1.f / shs[0];

#pragma unroll
    for (int i = 0; i < 4; i++) {
        float4 t;
        t.x = buf[i * 4 + 0] * r;
        t.y = buf[i * 4 + 1] * r;
        t.z = buf[i * 4 + 2] * r;
        t.w = buf[i * 4 + 3] * r;
        ((float4*)p)[i * 256 + tid] = t;
    }
}

// ---------------------------------------------------------------------------
extern "C" void kernel_launch(void* const* d_in, const int* in_sizes, int n_in,
                              void* d_out, int out_size) {
    const float* X[6];
    for (int i = 0; i < 6; i++) X[i] = (const float*)d_in[i];

    const float *W[6], *Bv[6];
    if (n_in >= 8 && in_sizes[7] == DD) {  // interleaved W,b
        for (int i = 0; i < 6; i++) {
            W[i]  = (const float*)d_in[6 + 2 * i];
            Bv[i] = (const float*)d_in[7 + 2 * i];
        }
    } else {  // grouped
        for (int i = 0; i < 6; i++) {
            W[i]  = (const float*)d_in[6 + i];
            Bv[i] = (const float*)d_in[12 + i];
        }
    }

    float* proj;
    float* score;
    cudaGetSymbolAddress((void**)&proj, g_proj);
    cudaGetSymbolAddress((void**)&score, g_score);

    float* P[6];
    for (int i = 0; i < 6; i++) P[i] = proj + (size_t)i * NC_ * DD;
    float* S1 = score;                      // [NC, NP]
    float* S2 = score + (size_t)NC_ * NP_;  // [NP, NC]

    cudaFuncSetAttribute(gemm_mma, cudaFuncAttributeMaxDynamicSharedMemorySize, GEMM_SMEM);
    dim3 blk(256);

    // q/k projections: P = X @ W^T + b (bias per column)
    {
        dim3 g(DD / 128, NC_ / 128);
        gemm_mma<<<g, blk, GEMM_SMEM>>>(X[0], W[0], Bv[0], P[0], NC_, DD, DD, 1);
        gemm_mma<<<g, blk, GEMM_SMEM>>>(X[1], W[1], Bv[1], P[1], NC_, DD, DD, 1);
        gemm_mma<<<g, blk, GEMM_SMEM>>>(X[3], W[3], Bv[3], P[3], NP_, DD, DD, 1);
        gemm_mma<<<g, blk, GEMM_SMEM>>>(X[4], W[4], Bv[4], P[4], NP_, DD, DD, 1);
    }
    // v projections TRANSPOSED: vT = Wv @ X^T + b (bias per row)
    {
        dim3 g(NC_ / 128, DD / 128);
        gemm_mma<<<g, blk, GEMM_SMEM>>>(W[2], X[2], Bv[2], P[2], DD, NC_, DD, 2);
        gemm_mma<<<g, blk, GEMM_SMEM>>>(W[5], X[5], Bv[5], P[5], DD, NP_, DD, 2);
    }
    // scores: S1 = qc @ kp^T, S2 = qp @ kc^T
    {
        dim3 g(NP_ / 128, NC_ / 128);
        gemm_mma<<<g, blk, GEMM_SMEM>>>(P[0], P[4], nullptr, S1, NC_, NP_, DD, 0);
        gemm_mma<<<g, blk, GEMM_SMEM>>>(P[3], P[1], nullptr, S2, NP_, NC_, DD, 0);
    }

    softmax4096<<<NC_, 256>>>(S1);
    softmax4096<<<NP_, 256>>>(S2);

    float* out = (float*)d_out;
    // comp = S1 @ vpT^T ; prot = S2 @ vcT^T
    {
        dim3 g(DD / 128, NC_ / 128);
        gemm_mma<<<g, blk, GEMM_SMEM>>>(S1, P[5], nullptr, out, NC_, DD, NP_, 0);
        gemm_mma<<<g, blk, GEMM_SMEM>>>(S2, P[2], nullptr, out + (size_t)NC_ * DD, NP_, DD, NC_, 0);
    }
}

// round 5
// speedup vs baseline: 3.2471x; 1.0932x over previous
#include <cuda_runtime.h>
#include <cstdint>

#define NC_ 4096
#define NP_ 4096
#define DD  1024

#define BM 128
#define BN 256
#define BK 32
#define LDA 36                                  // padded row stride (floats)
#define STAGES 3
#define STAGE_FLOATS ((BM + BN) * LDA)          // 384*36 = 13824
#define GEMM_SMEM (STAGES * STAGE_FLOATS * 4)   // 165888 B

// Scratch.
__device__ float g_proj[6][(size_t)NC_ * DD];    // projections (tf32-exact)
__device__ float g_score[2][(size_t)NC_ * NP_];  // scores / probs
__device__ float g_rx[6][(size_t)NC_ * DD];      // RNA-rounded inputs
__device__ float g_rw[6][(size_t)DD * DD];       // RNA-rounded weights

// ---------------------------------------------------------------------------
__device__ __forceinline__ void cp16(void* dst, const void* src) {
    uint32_t a;
    asm("{ .reg .u64 t; cvta.to.shared.u64 t, %1; cvt.u32.u64 %0, t; }"
        : "=r"(a) : "l"(dst));
    asm volatile("cp.async.cg.shared.global [%0], [%1], 16;" :: "r"(a), "l"(src));
}

__device__ __forceinline__ float rna(float x) {
    uint32_t r;
    asm("cvt.rna.tf32.f32 %0, %1;" : "=r"(r) : "f"(x));
    return __uint_as_float(r);
}

__device__ __forceinline__ void mma_tf32(float* d, const uint32_t* a, const uint32_t* b) {
    asm volatile(
        "mma.sync.aligned.m16n8k8.row.col.f32.tf32.tf32.f32 "
        "{%0,%1,%2,%3}, {%4,%5,%6,%7}, {%8,%9}, {%0,%1,%2,%3};"
        : "+f"(d[0]), "+f"(d[1]), "+f"(d[2]), "+f"(d[3])
        : "r"(a[0]), "r"(a[1]), "r"(a[2]), "r"(a[3]), "r"(b[0]), "r"(b[1]));
}

// ---------------------------------------------------------------------------
// Elementwise RNA tf32 rounding: out[i] = round_rna(in[i]).
// ---------------------------------------------------------------------------
__global__ __launch_bounds__(256)
void round_tf32(const float* __restrict__ in, float* __restrict__ out, int n4) {
    const int i = blockIdx.x * 256 + threadIdx.x;
    if (i < n4) {
        float4 v = ((const float4*)in)[i];
        v.x = rna(v.x); v.y = rna(v.y); v.z = rna(v.z); v.w = rna(v.w);
        ((float4*)out)[i] = v;
    }
}

// ---------------------------------------------------------------------------
// tf32 mma.sync NT GEMM: C[M,N] = A[M,K] * B[N,K]^T (+bias)
//   biasMode: 0=none, 1=bias[n] (per column), 2=bias[m] (per row)
//   roundOut: RNA-round outputs (when C feeds a later GEMM)
// 256 threads, 8 warps (2M x 4N), warp tile 64x64, CTA tile 128x256x32.
// Operands must already be tf32-exact; raw bits are fed to the MMA.
// ---------------------------------------------------------------------------
__global__ __launch_bounds__(256)
void gemm_mma(const float* __restrict__ A, const float* __restrict__ B,
              const float* __restrict__ bias, float* __restrict__ C,
              int M, int N, int K, int biasMode, int roundOut) {
    extern __shared__ float sm[];
    const int tid = threadIdx.x;
    const int wid = tid >> 5;
    const int lane = tid & 31;
    const int bx = blockIdx.x, by = blockIdx.y;
    const int T = K / BK;

    const float* gA = A + (size_t)(by * BM) * K;
    const float* gB = B + (size_t)(bx * BN) * K;

    const int lrow = tid >> 3;       // 0..31
    const int lq = (tid & 7) * 4;    // float offset within 32-float k-row

    auto load_tile = [&](int stage, int kt) {
        float* s = sm + stage * STAGE_FLOATS;
        const int kofs = kt * BK + lq;
#pragma unroll
        for (int l = 0; l < 4; l++) {  // A: rows 0..127
            const int row = l * 32 + lrow;
            cp16(s + row * LDA + lq, gA + (size_t)row * K + kofs);
        }
#pragma unroll
        for (int l = 0; l < 8; l++) {  // B: rows 0..255
            const int row = l * 32 + lrow;
            cp16(s + (BM + row) * LDA + lq, gB + (size_t)row * K + kofs);
        }
        asm volatile("cp.async.commit_group;" ::: "memory");
    };

    // prologue
    load_tile(0, 0);
    load_tile(1, 1);

    const int wm = wid & 1;   // 0..1 (M)
    const int wn = wid >> 1;  // 0..3 (N)
    const int r = lane >> 2;  // 0..7
    const int c = lane & 3;   // 0..3

    float acc[4][8][4] = {};

    for (int kt = 0; kt < T; kt++) {
        if (kt < T - 1)
            asm volatile("cp.async.wait_group 1;" ::: "memory");
        else
            asm volatile("cp.async.wait_group 0;" ::: "memory");
        __syncthreads();

        // issue next-next stage loads early (overlap DMA with MMA)
        if (kt + 2 < T) load_tile((kt + 2) % STAGES, kt + 2);

        const int stage = kt % STAGES;
        const uint32_t* sA = (const uint32_t*)(sm + stage * STAGE_FLOATS) +
                             (wm * 64 + r) * LDA + c;
        const uint32_t* sB = (const uint32_t*)(sm + stage * STAGE_FLOATS + BM * LDA) +
                             (wn * 64 + r) * LDA + c;

        uint32_t af[2][4][4], bf[2][8][2];

        // prefetch kk=0 fragments
#pragma unroll
        for (int mi = 0; mi < 4; mi++) {
            const uint32_t* p = sA + mi * 16 * LDA;
            af[0][mi][0] = p[0];
            af[0][mi][1] = p[8 * LDA];
            af[0][mi][2] = p[4];
            af[0][mi][3] = p[8 * LDA + 4];
        }
#pragma unroll
        for (int nj = 0; nj < 8; nj++) {
            const uint32_t* p = sB + nj * 8 * LDA;
            bf[0][nj][0] = p[0];
            bf[0][nj][1] = p[4];
        }

#pragma unroll
        for (int kk = 0; kk < 4; kk++) {
            const int cur = kk & 1;
            const int nxt = cur ^ 1;
            if (kk < 3) {
                const int k0 = (kk + 1) * 8;
#pragma unroll
                for (int mi = 0; mi < 4; mi++) {
                    const uint32_t* p = sA + mi * 16 * LDA + k0;
                    af[nxt][mi][0] = p[0];
                    af[nxt][mi][1] = p[8 * LDA];
                    af[nxt][mi][2] = p[4];
                    af[nxt][mi][3] = p[8 * LDA + 4];
                }
#pragma unroll
                for (int nj = 0; nj < 8; nj++) {
                    const uint32_t* p = sB + nj * 8 * LDA + k0;
                    bf[nxt][nj][0] = p[0];
                    bf[nxt][nj][1] = p[4];
                }
            }
#pragma unroll
            for (int mi = 0; mi < 4; mi++)
#pragma unroll
                for (int nj = 0; nj < 8; nj++)
                    mma_tf32(acc[mi][nj], af[cur][mi], bf[cur][nj]);
        }
    }

    // ---------------- epilogue ----------------
#pragma unroll
    for (int mi = 0; mi < 4; mi++) {
#pragma unroll
        for (int nj = 0; nj < 8; nj++) {
            const int row0 = by * BM + wm * 64 + mi * 16 + r;
            const int col = bx * BN + wn * 64 + nj * 8 + c * 2;
            float2 v0 = make_float2(acc[mi][nj][0], acc[mi][nj][1]);
            float2 v1 = make_float2(acc[mi][nj][2], acc[mi][nj][3]);
            if (biasMode == 1) {
                const float b0 = bias[col], b1 = bias[col + 1];
                v0.x += b0; v0.y += b1;
                v1.x += b0; v1.y += b1;
            } else if (biasMode == 2) {
                const float rb0 = bias[row0];
                const float rb1 = bias[row0 + 8];
                v0.x += rb0; v0.y += rb0;
                v1.x += rb1; v1.y += rb1;
            }
            if (roundOut) {
                v0.x = rna(v0.x); v0.y = rna(v0.y);
                v1.x = rna(v1.x); v1.y = rna(v1.y);
            }
            *(float2*)(C + (size_t)row0 * N + col) = v0;
            *(float2*)(C + (size_t)(row0 + 8) * N + col) = v1;
        }
    }
}

// ---------------------------------------------------------------------------
// In-place row softmax over 4096 columns (scale 1/32 folded in).
// Output probabilities are RNA-rounded (they feed the PV GEMM).
// ---------------------------------------------------------------------------
__global__ __launch_bounds__(256)
void softmax4096(float* __restrict__ S) {
    const int row = blockIdx.x;
    float* p = S + (size_t)row * 4096;
    const int tid = threadIdx.x;
    const float isc = 0.03125f;  // 1/sqrt(1024)

    __shared__ float shm[8];
    __shared__ float shs[8];

    float buf[16];
    float m = -1e30f;
#pragma unroll
    for (int i = 0; i < 4; i++) {
        float4 t = ((const float4*)p)[i * 256 + tid];
        buf[i * 4 + 0] = t.x * isc;
        buf[i * 4 + 1] = t.y * isc;
        buf[i * 4 + 2] = t.z * isc;
        buf[i * 4 + 3] = t.w * isc;
        m = fmaxf(m, fmaxf(fmaxf(buf[i * 4], buf[i * 4 + 1]),
                           fmaxf(buf[i * 4 + 2], buf[i * 4 + 3])));
    }
#pragma unroll
    for (int o = 16; o; o >>= 1) m = fmaxf(m, __shfl_xor_sync(0xffffffffu, m, o));
    if ((tid & 31) == 0) shm[tid >> 5] = m;
    __syncthreads();
    if (tid == 0) {
        float mm = shm[0];
#pragma unroll
        for (int w = 1; w < 8; w++) mm = fmaxf(mm, shm[w]);
        shm[0] = mm;
    }
    __syncthreads();
    m = shm[0];

    float s = 0.f;
#pragma unroll
    for (int i = 0; i < 16; i++) {
        float e = __expf(buf[i] - m);
        buf[i] = e;
        s += e;
    }
#pragma unroll
    for (int o = 16; o; o >>= 1) s += __shfl_xor_sync(0xffffffffu, s, o);
    if ((tid & 31) == 0) shs[tid >> 5] = s;
    __syncthreads();
    if (tid == 0) {
        float ss = shs[0];
#pragma unroll
        for (int w = 1; w < 8; w++) ss += shs[w];
        shs[0] = ss;
    }
    __syncthreads();
    const float r = 1.f / shs[0];

#pragma unroll
    for (int i = 0; i < 4; i++) {
        float4 t;
        t.x = rna(buf[i * 4 + 0] * r);
        t.y = rna(buf[i * 4 + 1] * r);
        t.z = rna(buf[i * 4 + 2] * r);
        t.w = rna(buf[i * 4 + 3] * r);
        ((float4*)p)[i * 256 + tid] = t;
    }
}

// ---------------------------------------------------------------------------
extern "C" void kernel_launch(void* const* d_in, const int* in_sizes, int n_in,
                              void* d_out, int out_size) {
    const float* X[6];
    for (int i = 0; i < 6; i++) X[i] = (const float*)d_in[i];

    const float *W[6], *Bv[6];
    if (n_in >= 8 && in_sizes[7] == DD) {  // interleaved W,b
        for (int i = 0; i < 6; i++) {
            W[i]  = (const float*)d_in[6 + 2 * i];
            Bv[i] = (const float*)d_in[7 + 2 * i];
        }
    } else {  // grouped
        for (int i = 0; i < 6; i++) {
            W[i]  = (const float*)d_in[6 + i];
            Bv[i] = (const float*)d_in[12 + i];
        }
    }

    float *proj, *score, *rx, *rw;
    cudaGetSymbolAddress((void**)&proj, g_proj);
    cudaGetSymbolAddress((void**)&score, g_score);
    cudaGetSymbolAddress((void**)&rx, g_rx);
    cudaGetSymbolAddress((void**)&rw, g_rw);

    float* P[6];
    for (int i = 0; i < 6; i++) P[i] = proj + (size_t)i * NC_ * DD;
    float* RX[6];
    for (int i = 0; i < 6; i++) RX[i] = rx + (size_t)i * NC_ * DD;
    float* RW[6];
    for (int i = 0; i < 6; i++) RW[i] = rw + (size_t)i * DD * DD;
    float* S1 = score;                      // [NC, NP]
    float* S2 = score + (size_t)NC_ * NP_;  // [NP, NC]

    // Pre-round inputs & weights to tf32-exact values.
    {
        const int nx4 = NC_ * DD / 4, nw4 = DD * DD / 4;
        for (int i = 0; i < 6; i++) {
            round_tf32<<<(nx4 + 255) / 256, 256>>>(X[i], RX[i], nx4);
            round_tf32<<<(nw4 + 255) / 256, 256>>>(W[i], RW[i], nw4);
        }
    }

    cudaFuncSetAttribute(gemm_mma, cudaFuncAttributeMaxDynamicSharedMemorySize, GEMM_SMEM);
    dim3 blk(256);

    // q/k projections: P = X @ W^T + b (bias per column), rounded outputs
    {
        dim3 g(DD / BN, NC_ / BM);
        gemm_mma<<<g, blk, GEMM_SMEM>>>(RX[0], RW[0], Bv[0], P[0], NC_, DD, DD, 1, 1);
        gemm_mma<<<g, blk, GEMM_SMEM>>>(RX[1], RW[1], Bv[1], P[1], NC_, DD, DD, 1, 1);
        gemm_mma<<<g, blk, GEMM_SMEM>>>(RX[3], RW[3], Bv[3], P[3], NP_, DD, DD, 1, 1);
        gemm_mma<<<g, blk, GEMM_SMEM>>>(RX[4], RW[4], Bv[4], P[4], NP_, DD, DD, 1, 1);
    }
    // v projections TRANSPOSED: vT = Wv @ X^T + b (bias per row), rounded outputs
    {
        dim3 g(NC_ / BN, DD / BM);
        gemm_mma<<<g, blk, GEMM_SMEM>>>(RW[2], RX[2], Bv[2], P[2], DD, NC_, DD, 2, 1);
        gemm_mma<<<g, blk, GEMM_SMEM>>>(RW[5], RX[5], Bv[5], P[5], DD, NP_, DD, 2, 1);
    }
    // scores: S1 = qc @ kp^T, S2 = qp @ kc^T (no rounding; softmax rounds)
    {
        dim3 g(NP_ / BN, NC_ / BM);
        gemm_mma<<<g, blk, GEMM_SMEM>>>(P[0], P[4], nullptr, S1, NC_, NP_, DD, 0, 0);
        gemm_mma<<<g, blk, GEMM_SMEM>>>(P[3], P[1], nullptr, S2, NP_, NC_, DD, 0, 0);
    }

    softmax4096<<<NC_, 256>>>(S1);
    softmax4096<<<NP_, 256>>>(S2);

    float* out = (float*)d_out;
    // comp = S1 @ vpT^T ; prot = S2 @ vcT^T (final outputs, no rounding)
    {
        dim3 g(DD / BN, NC_ / BM);
        gemm_mma<<<g, blk, GEMM_SMEM>>>(S1, P[5], nullptr, out, NC_, DD, NP_, 0, 0);
        gemm_mma<<<g, blk, GEMM_SMEM>>>(S2, P[2], nullptr, out + (size_t)NC_ * DD, NP_, DD, NC_, 0, 0);
    }
}

// round 6
// speedup vs baseline: 5.7778x; 1.7794x over previous
#include <cuda_runtime.h>
#include <cuda_fp16.h>
#include <cstdint>

#define NC_ 4096
#define NP_ 4096
#define DD  1024

#define BM 128
#define BN 128
#define BK 64                                    // fp16 elements per k-tile
#define LDH 72                                   // padded row stride (halves)
#define STAGES 3
#define STAGE_HALVES ((BM + BN) * LDH)           // 256*72 = 18432 halves
#define GEMM_SMEM (STAGES * STAGE_HALVES * 2)    // 110592 B

// Scratch.
__device__ __half g_xh[6][(size_t)NC_ * DD];     // fp16 inputs
__device__ __half g_wh[6][(size_t)DD * DD];      // fp16 weights
__device__ __half g_ph[6][(size_t)NC_ * DD];     // fp16 projections (q,k,vT)
__device__ float  g_score[2][(size_t)NC_ * NP_]; // fp32 scores
__device__ __half g_prob[2][(size_t)NC_ * NP_];  // fp16 probabilities

// ---------------------------------------------------------------------------
__device__ __forceinline__ void cp16(void* dst, const void* src) {
    uint32_t a;
    asm("{ .reg .u64 t; cvta.to.shared.u64 t, %1; cvt.u32.u64 %0, t; }"
        : "=r"(a) : "l"(dst));
    asm volatile("cp.async.cg.shared.global [%0], [%1], 16;" :: "r"(a), "l"(src));
}

__device__ __forceinline__ void mma_f16(float* d, const uint32_t* a, const uint32_t* b) {
    asm volatile(
        "mma.sync.aligned.m16n8k16.row.col.f32.f16.f16.f32 "
        "{%0,%1,%2,%3}, {%4,%5,%6,%7}, {%8,%9}, {%0,%1,%2,%3};"
        : "+f"(d[0]), "+f"(d[1]), "+f"(d[2]), "+f"(d[3])
        : "r"(a[0]), "r"(a[1]), "r"(a[2]), "r"(a[3]), "r"(b[0]), "r"(b[1]));
}

// ---------------------------------------------------------------------------
// fp32 -> fp16 conversion (RNE), 4 elems/thread.
// ---------------------------------------------------------------------------
__global__ __launch_bounds__(256)
void conv_h(const float* __restrict__ in, __half* __restrict__ out, int n4) {
    const int i = blockIdx.x * 256 + threadIdx.x;
    if (i < n4) {
        float4 v = ((const float4*)in)[i];
        ((__half2*)out)[2 * i + 0] = __floats2half2_rn(v.x, v.y);
        ((__half2*)out)[2 * i + 1] = __floats2half2_rn(v.z, v.w);
    }
}

// ---------------------------------------------------------------------------
// fp16 mma.sync NT GEMM: C[M,N] = A[M,K] * B[N,K]^T (+bias), fp32 accumulate.
//   biasMode: 0=none, 1=bias[n], 2=bias[m];   outHalf: store __half else float
// 256 threads, 8 warps (2M x 4N), warp tile 64x32, CTA tile 128x128x64.
// ---------------------------------------------------------------------------
__global__ __launch_bounds__(256)
void gemm_h(const __half* __restrict__ A, const __half* __restrict__ B,
            const float* __restrict__ bias, void* __restrict__ Cv,
            int M, int N, int K, int biasMode, int outHalf) {
    extern __shared__ __half smh[];
    const int tid = threadIdx.x;
    const int wid = tid >> 5;
    const int lane = tid & 31;
    const int bx = blockIdx.x, by = blockIdx.y;
    const int T = K / BK;

    const __half* gA = A + (size_t)(by * BM) * K;
    const __half* gB = B + (size_t)(bx * BN) * K;

    const int lrow = tid >> 3;        // 0..31
    const int lq = (tid & 7) * 8;     // half offset within 64-half row

    auto load_tile = [&](int stage, int kt) {
        __half* s = smh + stage * STAGE_HALVES;
        const int kofs = kt * BK + lq;
#pragma unroll
        for (int l = 0; l < 4; l++) {  // A rows 0..127
            const int row = l * 32 + lrow;
            cp16(s + row * LDH + lq, gA + (size_t)row * K + kofs);
        }
#pragma unroll
        for (int l = 0; l < 4; l++) {  // B rows 0..127
            const int row = l * 32 + lrow;
            cp16(s + (BM + row) * LDH + lq, gB + (size_t)row * K + kofs);
        }
        asm volatile("cp.async.commit_group;" ::: "memory");
    };

    load_tile(0, 0);
    load_tile(1, 1);

    const int wm = wid & 1;   // 0..1 (M)
    const int wn = wid >> 1;  // 0..3 (N)
    const int r = lane >> 2;  // 0..7
    const int c = lane & 3;   // 0..3

    float acc[4][4][4] = {};

    for (int kt = 0; kt < T; kt++) {
        if (kt < T - 1)
            asm volatile("cp.async.wait_group 1;" ::: "memory");
        else
            asm volatile("cp.async.wait_group 0;" ::: "memory");
        __syncthreads();

        if (kt + 2 < T) load_tile((kt + 2) % STAGES, kt + 2);

        const int stage = kt % STAGES;
        // word (uint32) view: LDH halves = 36 words per row
        const uint32_t* sA = (const uint32_t*)(smh + stage * STAGE_HALVES) +
                             (wm * 64 + r) * 36 + c;
        const uint32_t* sB = (const uint32_t*)(smh + stage * STAGE_HALVES + BM * LDH) +
                             (wn * 32 + r) * 36 + c;

        uint32_t af[2][4][4], bf[2][4][2];

        // prefetch kk=0 fragments
#pragma unroll
        for (int mi = 0; mi < 4; mi++) {
            const uint32_t* p = sA + mi * 16 * 36;
            af[0][mi][0] = p[0];
            af[0][mi][1] = p[8 * 36];
            af[0][mi][2] = p[4];
            af[0][mi][3] = p[8 * 36 + 4];
        }
#pragma unroll
        for (int nj = 0; nj < 4; nj++) {
            const uint32_t* p = sB + nj * 8 * 36;
            bf[0][nj][0] = p[0];
            bf[0][nj][1] = p[4];
        }

#pragma unroll
        for (int kk = 0; kk < 4; kk++) {       // 4 x k16 steps per k-tile
            const int cur = kk & 1;
            const int nxt = cur ^ 1;
            if (kk < 3) {
                const int k0 = (kk + 1) * 8;   // word offset = 8 per k16
#pragma unroll
                for (int mi = 0; mi < 4; mi++) {
                    const uint32_t* p = sA + mi * 16 * 36 + k0;
                    af[nxt][mi][0] = p[0];
                    af[nxt][mi][1] = p[8 * 36];
                    af[nxt][mi][2] = p[4];
                    af[nxt][mi][3] = p[8 * 36 + 4];
                }
#pragma unroll
                for (int nj = 0; nj < 4; nj++) {
                    const uint32_t* p = sB + nj * 8 * 36 + k0;
                    bf[nxt][nj][0] = p[0];
                    bf[nxt][nj][1] = p[4];
                }
            }
#pragma unroll
            for (int mi = 0; mi < 4; mi++)
#pragma unroll
                for (int nj = 0; nj < 4; nj++)
                    mma_f16(acc[mi][nj], af[cur][mi], bf[cur][nj]);
        }
    }

    // ---------------- epilogue ----------------
#pragma unroll
    for (int mi = 0; mi < 4; mi++) {
#pragma unroll
        for (int nj = 0; nj < 4; nj++) {
            const int row0 = by * BM + wm * 64 + mi * 16 + r;
            const int col = bx * BN + wn * 32 + nj * 8 + c * 2;
            float2 v0 = make_float2(acc[mi][nj][0], acc[mi][nj][1]);
            float2 v1 = make_float2(acc[mi][nj][2], acc[mi][nj][3]);
            if (biasMode == 1) {
                const float b0 = bias[col], b1 = bias[col + 1];
                v0.x += b0; v0.y += b1;
                v1.x += b0; v1.y += b1;
            } else if (biasMode == 2) {
                const float rb0 = bias[row0];
                const float rb1 = bias[row0 + 8];
                v0.x += rb0; v0.y += rb0;
                v1.x += rb1; v1.y += rb1;
            }
            if (outHalf) {
                __half* C = (__half*)Cv;
                *(__half2*)(C + (size_t)row0 * N + col) = __floats2half2_rn(v0.x, v0.y);
                *(__half2*)(C + (size_t)(row0 + 8) * N + col) = __floats2half2_rn(v1.x, v1.y);
            } else {
                float* C = (float*)Cv;
                *(float2*)(C + (size_t)row0 * N + col) = v0;
                *(float2*)(C + (size_t)(row0 + 8) * N + col) = v1;
            }
        }
    }
}

// ---------------------------------------------------------------------------
// Row softmax over 4096 columns: fp32 scores in, fp16 probs out (scale 1/32).
// ---------------------------------------------------------------------------
__global__ __launch_bounds__(256)
void softmax4096(const float* __restrict__ S, __half* __restrict__ P) {
    const int row = blockIdx.x;
    const float* p = S + (size_t)row * 4096;
    __half* q = P + (size_t)row * 4096;
    const int tid = threadIdx.x;
    const float isc = 0.03125f;  // 1/sqrt(1024)

    __shared__ float shm[8];
    __shared__ float shs[8];

    float buf[16];
    float m = -1e30f;
#pragma unroll
    for (int i = 0; i < 4; i++) {
        float4 t = ((const float4*)p)[i * 256 + tid];
        buf[i * 4 + 0] = t.x * isc;
        buf[i * 4 + 1] = t.y * isc;
        buf[i * 4 + 2] = t.z * isc;
        buf[i * 4 + 3] = t.w * isc;
        m = fmaxf(m, fmaxf(fmaxf(buf[i * 4], buf[i * 4 + 1]),
                           fmaxf(buf[i * 4 + 2], buf[i * 4 + 3])));
    }
#pragma unroll
    for (int o = 16; o; o >>= 1) m = fmaxf(m, __shfl_xor_sync(0xffffffffu, m, o));
    if ((tid & 31) == 0) shm[tid >> 5] = m;
    __syncthreads();
    if (tid == 0) {
        float mm = shm[0];
#pragma unroll
        for (int w = 1; w < 8; w++) mm = fmaxf(mm, shm[w]);
        shm[0] = mm;
    }
    __syncthreads();
    m = shm[0];

    float s = 0.f;
#pragma unroll
    for (int i = 0; i < 16; i++) {
        float e = __expf(buf[i] - m);
        buf[i] = e;
        s += e;
    }
#pragma unroll
    for (int o = 16; o; o >>= 1) s += __shfl_xor_sync(0xffffffffu, s, o);
    if ((tid & 31) == 0) shs[tid >> 5] = s;
    __syncthreads();
    if (tid == 0) {
        float ss = shs[0];
#pragma unroll
        for (int w = 1; w < 8; w++) ss += shs[w];
        shs[0] = ss;
    }
    __syncthreads();
    const float r = 1.f / shs[0];

#pragma unroll
    for (int i = 0; i < 4; i++) {
        __half2 h0 = __floats2half2_rn(buf[i * 4 + 0] * r, buf[i * 4 + 1] * r);
        __half2 h1 = __floats2half2_rn(buf[i * 4 + 2] * r, buf[i * 4 + 3] * r);
        ((__half2*)q)[(i * 256 + tid) * 2 + 0] = h0;
        ((__half2*)q)[(i * 256 + tid) * 2 + 1] = h1;
    }
}

// ---------------------------------------------------------------------------
extern "C" void kernel_launch(void* const* d_in, const int* in_sizes, int n_in,
                              void* d_out, int out_size) {
    const float* X[6];
    for (int i = 0; i < 6; i++) X[i] = (const float*)d_in[i];

    const float *W[6], *Bv[6];
    if (n_in >= 8 && in_sizes[7] == DD) {  // interleaved W,b
        for (int i = 0; i < 6; i++) {
            W[i]  = (const float*)d_in[6 + 2 * i];
            Bv[i] = (const float*)d_in[7 + 2 * i];
        }
    } else {  // grouped
        for (int i = 0; i < 6; i++) {
            W[i]  = (const float*)d_in[6 + i];
            Bv[i] = (const float*)d_in[12 + i];
        }
    }

    __half *xh, *wh, *ph, *prob;
    float* score;
    cudaGetSymbolAddress((void**)&xh, g_xh);
    cudaGetSymbolAddress((void**)&wh, g_wh);
    cudaGetSymbolAddress((void**)&ph, g_ph);
    cudaGetSymbolAddress((void**)&score, g_score);
    cudaGetSymbolAddress((void**)&prob, g_prob);

    __half* XH[6];
    __half* WH[6];
    __half* PH[6];
    for (int i = 0; i < 6; i++) {
        XH[i] = xh + (size_t)i * NC_ * DD;
        WH[i] = wh + (size_t)i * DD * DD;
        PH[i] = ph + (size_t)i * NC_ * DD;
    }
    float* S1 = score;                      // [NC, NP]
    float* S2 = score + (size_t)NC_ * NP_;  // [NP, NC]
    __half* P1 = prob;
    __half* P2 = prob + (size_t)NC_ * NP_;

    // fp32 -> fp16 conversion of inputs & weights
    {
        const int nx4 = NC_ * DD / 4, nw4 = DD * DD / 4;
        for (int i = 0; i < 6; i++) {
            conv_h<<<(nx4 + 255) / 256, 256>>>(X[i], XH[i], nx4);
            conv_h<<<(nw4 + 255) / 256, 256>>>(W[i], WH[i], nw4);
        }
    }

    cudaFuncSetAttribute(gemm_h, cudaFuncAttributeMaxDynamicSharedMemorySize, GEMM_SMEM);
    dim3 blk(256);

    // q/k projections -> fp16 (bias per column)
    {
        dim3 g(DD / BN, NC_ / BM);
        gemm_h<<<g, blk, GEMM_SMEM>>>(XH[0], WH[0], Bv[0], PH[0], NC_, DD, DD, 1, 1);
        gemm_h<<<g, blk, GEMM_SMEM>>>(XH[1], WH[1], Bv[1], PH[1], NC_, DD, DD, 1, 1);
        gemm_h<<<g, blk, GEMM_SMEM>>>(XH[3], WH[3], Bv[3], PH[3], NP_, DD, DD, 1, 1);
        gemm_h<<<g, blk, GEMM_SMEM>>>(XH[4], WH[4], Bv[4], PH[4], NP_, DD, DD, 1, 1);
    }
    // v projections TRANSPOSED -> fp16: vT = Wv @ X^T + b (bias per row)
    {
        dim3 g(NC_ / BN, DD / BM);
        gemm_h<<<g, blk, GEMM_SMEM>>>(WH[2], XH[2], Bv[2], PH[2], DD, NC_, DD, 2, 1);
        gemm_h<<<g, blk, GEMM_SMEM>>>(WH[5], XH[5], Bv[5], PH[5], DD, NP_, DD, 2, 1);
    }
    // scores -> fp32: S1 = qc @ kp^T, S2 = qp @ kc^T
    {
        dim3 g(NP_ / BN, NC_ / BM);
        gemm_h<<<g, blk, GEMM_SMEM>>>(PH[0], PH[4], nullptr, S1, NC_, NP_, DD, 0, 0);
        gemm_h<<<g, blk, GEMM_SMEM>>>(PH[3], PH[1], nullptr, S2, NP_, NC_, DD, 0, 0);
    }

    softmax4096<<<NC_, 256>>>(S1, P1);
    softmax4096<<<NP_, 256>>>(S2, P2);

    float* out = (float*)d_out;
    // comp = P1 @ vpT^T ; prot = P2 @ vcT^T  (fp32 outputs)
    {
        dim3 g(DD / BN, NC_ / BM);
        gemm_h<<<g, blk, GEMM_SMEM>>>(P1, PH[5], nullptr, out, NC_, DD, NP_, 0, 0);
        gemm_h<<<g, blk, GEMM_SMEM>>>(P2, PH[2], nullptr, out + (size_t)NC_ * DD, NP_, DD, NC_, 0, 0);
    }
}

// round 7
// speedup vs baseline: 7.2983x; 1.2632x over previous
#include <cuda_runtime.h>
#include <cuda_fp16.h>
#include <cstdint>

#define NC_ 4096
#define NP_ 4096
#define DD  1024

#define BM 128
#define BN 128
#define BK 64                                    // fp16 elements per k-tile
#define STAGE_BYTES 32768                        // (128 A + 128 B) rows x 128 B
#define STAGES 3
#define GEMM_SMEM (STAGES * STAGE_BYTES)         // 98304 B

// Scratch.
__device__ __half g_xh[6][(size_t)NC_ * DD];     // fp16 inputs
__device__ __half g_wh[6][(size_t)DD * DD];      // fp16 weights
__device__ __half g_ph[6][(size_t)NC_ * DD];     // fp16 projections (q,k,vT)
__device__ float  g_score[2][(size_t)NC_ * NP_]; // fp32 scores
__device__ __half g_prob[2][(size_t)NC_ * NP_];  // fp16 probabilities

// ---------------------------------------------------------------------------
__device__ __forceinline__ uint32_t smem_u32(const void* p) {
    uint32_t a;
    asm("{ .reg .u64 t; cvta.to.shared.u64 t, %1; cvt.u32.u64 %0, t; }"
        : "=r"(a) : "l"(p));
    return a;
}

__device__ __forceinline__ void cp16u(uint32_t dst, const void* src) {
    asm volatile("cp.async.cg.shared.global [%0], [%1], 16;" :: "r"(dst), "l"(src));
}

__device__ __forceinline__ void ldsm_x4(uint32_t addr, uint32_t* r) {
    asm volatile("ldmatrix.sync.aligned.m8n8.x4.shared.b16 {%0,%1,%2,%3}, [%4];"
                 : "=r"(r[0]), "=r"(r[1]), "=r"(r[2]), "=r"(r[3]) : "r"(addr));
}

__device__ __forceinline__ void mma_f16(float* d, const uint32_t* a, const uint32_t* b) {
    asm volatile(
        "mma.sync.aligned.m16n8k16.row.col.f32.f16.f16.f32 "
        "{%0,%1,%2,%3}, {%4,%5,%6,%7}, {%8,%9}, {%0,%1,%2,%3};"
        : "+f"(d[0]), "+f"(d[1]), "+f"(d[2]), "+f"(d[3])
        : "r"(a[0]), "r"(a[1]), "r"(a[2]), "r"(a[3]), "r"(b[0]), "r"(b[1]));
}

// ---------------------------------------------------------------------------
// fp32 -> fp16 conversion (RNE), 4 elems/thread.
// ---------------------------------------------------------------------------
__global__ __launch_bounds__(256)
void conv_h(const float* __restrict__ in, __half* __restrict__ out, int n4) {
    const int i = blockIdx.x * 256 + threadIdx.x;
    if (i < n4) {
        float4 v = ((const float4*)in)[i];
        ((__half2*)out)[2 * i + 0] = __floats2half2_rn(v.x, v.y);
        ((__half2*)out)[2 * i + 1] = __floats2half2_rn(v.z, v.w);
    }
}

// ---------------------------------------------------------------------------
// fp16 mma.sync NT GEMM: C[M,N] = A[M,K] * B[N,K]^T (+bias), fp32 accumulate.
//   biasMode: 0=none, 1=bias[n], 2=bias[m];   outHalf: store __half else float
// 256 threads, 8 warps (2M x 4N), warp tile 64x32, CTA tile 128x128x64.
// SMEM: 128-byte rows, XOR-swizzled; fragments via ldmatrix.x4. 2 CTAs/SM.
// ---------------------------------------------------------------------------
__global__ __launch_bounds__(256, 2)
void gemm_h(const __half* __restrict__ A, const __half* __restrict__ B,
            const float* __restrict__ bias, void* __restrict__ Cv,
            int M, int N, int K, int biasMode, int outHalf) {
    extern __shared__ __half smh[];
    const uint32_t sbase = smem_u32(smh);
    const int tid = threadIdx.x;
    const int wid = tid >> 5;
    const int lane = tid & 31;
    const int bx = blockIdx.x, by = blockIdx.y;
    const int T = K / BK;

    const __half* gA = A + (size_t)(by * BM) * K;
    const __half* gB = B + (size_t)(bx * BN) * K;

    // producer addressing: each thread stores 16B at (row, chunk)
    const int srow = tid >> 3;                       // 0..31
    const int schunk = tid & 7;                      // 16B chunk in 128B row
    const uint32_t ssw = (uint32_t)((schunk ^ (srow & 7)) << 4);

    auto load_tile = [&](int stage, int kt) {
        const uint32_t s = sbase + stage * STAGE_BYTES;
        const int kofs = kt * BK + schunk * 8;
#pragma unroll
        for (int l = 0; l < 4; l++) {  // A rows
            const int row = l * 32 + srow;
            cp16u(s + row * 128 + ssw, gA + (size_t)row * K + kofs);
        }
#pragma unroll
        for (int l = 0; l < 4; l++) {  // B rows
            const int row = l * 32 + srow;
            cp16u(s + 16384 + row * 128 + ssw, gB + (size_t)row * K + kofs);
        }
        asm volatile("cp.async.commit_group;" ::: "memory");
    };

    load_tile(0, 0);
    load_tile(1, 1);

    const int wm = wid & 1;   // 0..1 (M)
    const int wn = wid >> 1;  // 0..3 (N)
    const int lane7 = lane & 7;

    // ldmatrix per-lane row indices (swizzle XOR reduces to lane7)
    const int aRow = wm * 64 + ((lane >> 3) & 1) * 8 + lane7;   // + mi*16
    const int bRow = wn * 32 + ((lane >> 4) & 1) * 8 + lane7;   // + p*16
    const int aHi = lane >> 4;
    const int bHi = (lane >> 3) & 1;
    uint32_t aCol[4], bCol[4];
#pragma unroll
    for (int kk = 0; kk < 4; kk++) {
        aCol[kk] = (uint32_t)(((2 * kk + aHi) ^ lane7) << 4);
        bCol[kk] = (uint32_t)(((2 * kk + bHi) ^ lane7) << 4);
    }

    float acc[4][4][4] = {};

    for (int kt = 0; kt < T; kt++) {
        if (kt < T - 1)
            asm volatile("cp.async.wait_group 1;" ::: "memory");
        else
            asm volatile("cp.async.wait_group 0;" ::: "memory");
        __syncthreads();

        if (kt + 2 < T) load_tile((kt + 2) % STAGES, kt + 2);

        const uint32_t sA = sbase + (kt % STAGES) * STAGE_BYTES;
        const uint32_t sB = sA + 16384;

#pragma unroll
        for (int kk = 0; kk < 4; kk++) {   // 4 x k16 per k-tile
            uint32_t a[4][4], b[2][4];
#pragma unroll
            for (int mi = 0; mi < 4; mi++)
                ldsm_x4(sA + (aRow + mi * 16) * 128 + aCol[kk], a[mi]);
#pragma unroll
            for (int p = 0; p < 2; p++)
                ldsm_x4(sB + (bRow + p * 16) * 128 + bCol[kk], b[p]);
#pragma unroll
            for (int mi = 0; mi < 4; mi++)
#pragma unroll
                for (int nj = 0; nj < 4; nj++)
                    mma_f16(acc[mi][nj], a[mi], &b[nj >> 1][(nj & 1) * 2]);
        }
    }

    // ---------------- epilogue ----------------
    const int r = lane >> 2;  // 0..7
    const int c = lane & 3;   // 0..3
#pragma unroll
    for (int mi = 0; mi < 4; mi++) {
#pragma unroll
        for (int nj = 0; nj < 4; nj++) {
            const int row0 = by * BM + wm * 64 + mi * 16 + r;
            const int col = bx * BN + wn * 32 + nj * 8 + c * 2;
            float2 v0 = make_float2(acc[mi][nj][0], acc[mi][nj][1]);
            float2 v1 = make_float2(acc[mi][nj][2], acc[mi][nj][3]);
            if (biasMode == 1) {
                const float b0 = bias[col], b1 = bias[col + 1];
                v0.x += b0; v0.y += b1;
                v1.x += b0; v1.y += b1;
            } else if (biasMode == 2) {
                const float rb0 = bias[row0];
                const float rb1 = bias[row0 + 8];
                v0.x += rb0; v0.y += rb0;
                v1.x += rb1; v1.y += rb1;
            }
            if (outHalf) {
                __half* C = (__half*)Cv;
                *(__half2*)(C + (size_t)row0 * N + col) = __floats2half2_rn(v0.x, v0.y);
                *(__half2*)(C + (size_t)(row0 + 8) * N + col) = __floats2half2_rn(v1.x, v1.y);
            } else {
                float* C = (float*)Cv;
                *(float2*)(C + (size_t)row0 * N + col) = v0;
                *(float2*)(C + (size_t)(row0 + 8) * N + col) = v1;
            }
        }
    }
}

// ---------------------------------------------------------------------------
// Row softmax over 4096 columns: fp32 scores in, fp16 probs out (scale 1/32).
// ---------------------------------------------------------------------------
__global__ __launch_bounds__(256)
void softmax4096(const float* __restrict__ S, __half* __restrict__ P) {
    const int row = blockIdx.x;
    const float* p = S + (size_t)row * 4096;
    __half* q = P + (size_t)row * 4096;
    const int tid = threadIdx.x;
    const float isc = 0.03125f;  // 1/sqrt(1024)

    __shared__ float shm[8];
    __shared__ float shs[8];

    float buf[16];
    float m = -1e30f;
#pragma unroll
    for (int i = 0; i < 4; i++) {
        float4 t = ((const float4*)p)[i * 256 + tid];
        buf[i * 4 + 0] = t.x * isc;
        buf[i * 4 + 1] = t.y * isc;
        buf[i * 4 + 2] = t.z * isc;
        buf[i * 4 + 3] = t.w * isc;
        m = fmaxf(m, fmaxf(fmaxf(buf[i * 4], buf[i * 4 + 1]),
                           fmaxf(buf[i * 4 + 2], buf[i * 4 + 3])));
    }
#pragma unroll
    for (int o = 16; o; o >>= 1) m = fmaxf(m, __shfl_xor_sync(0xffffffffu, m, o));
    if ((tid & 31) == 0) shm[tid >> 5] = m;
    __syncthreads();
    if (tid == 0) {
        float mm = shm[0];
#pragma unroll
        for (int w = 1; w < 8; w++) mm = fmaxf(mm, shm[w]);
        shm[0] = mm;
    }
    __syncthreads();
    m = shm[0];

    float s = 0.f;
#pragma unroll
    for (int i = 0; i < 16; i++) {
        float e = __expf(buf[i] - m);
        buf[i] = e;
        s += e;
    }
#pragma unroll
    for (int o = 16; o; o >>= 1) s += __shfl_xor_sync(0xffffffffu, s, o);
    if ((tid & 31) == 0) shs[tid >> 5] = s;
    __syncthreads();
    if (tid == 0) {
        float ss = shs[0];
#pragma unroll
        for (int w = 1; w < 8; w++) ss += shs[w];
        shs[0] = ss;
    }
    __syncthreads();
    const float r = 1.f / shs[0];

#pragma unroll
    for (int i = 0; i < 4; i++) {
        __half2 h0 = __floats2half2_rn(buf[i * 4 + 0] * r, buf[i * 4 + 1] * r);
        __half2 h1 = __floats2half2_rn(buf[i * 4 + 2] * r, buf[i * 4 + 3] * r);
        ((__half2*)q)[(i * 256 + tid) * 2 + 0] = h0;
        ((__half2*)q)[(i * 256 + tid) * 2 + 1] = h1;
    }
}

// ---------------------------------------------------------------------------
extern "C" void kernel_launch(void* const* d_in, const int* in_sizes, int n_in,
                              void* d_out, int out_size) {
    const float* X[6];
    for (int i = 0; i < 6; i++) X[i] = (const float*)d_in[i];

    const float *W[6], *Bv[6];
    if (n_in >= 8 && in_sizes[7] == DD) {  // interleaved W,b
        for (int i = 0; i < 6; i++) {
            W[i]  = (const float*)d_in[6 + 2 * i];
            Bv[i] = (const float*)d_in[7 + 2 * i];
        }
    } else {  // grouped
        for (int i = 0; i < 6; i++) {
            W[i]  = (const float*)d_in[6 + i];
            Bv[i] = (const float*)d_in[12 + i];
        }
    }

    __half *xh, *wh, *ph, *prob;
    float* score;
    cudaGetSymbolAddress((void**)&xh, g_xh);
    cudaGetSymbolAddress((void**)&wh, g_wh);
    cudaGetSymbolAddress((void**)&ph, g_ph);
    cudaGetSymbolAddress((void**)&score, g_score);
    cudaGetSymbolAddress((void**)&prob, g_prob);

    __half* XH[6];
    __half* WH[6];
    __half* PH[6];
    for (int i = 0; i < 6; i++) {
        XH[i] = xh + (size_t)i * NC_ * DD;
        WH[i] = wh + (size_t)i * DD * DD;
        PH[i] = ph + (size_t)i * NC_ * DD;
    }
    float* S1 = score;                      // [NC, NP]
    float* S2 = score + (size_t)NC_ * NP_;  // [NP, NC]
    __half* P1 = prob;
    __half* P2 = prob + (size_t)NC_ * NP_;

    // fp32 -> fp16 conversion of inputs & weights
    {
        const int nx4 = NC_ * DD / 4, nw4 = DD * DD / 4;
        for (int i = 0; i < 6; i++) {
            conv_h<<<(nx4 + 255) / 256, 256>>>(X[i], XH[i], nx4);
            conv_h<<<(nw4 + 255) / 256, 256>>>(W[i], WH[i], nw4);
        }
    }

    cudaFuncSetAttribute(gemm_h, cudaFuncAttributeMaxDynamicSharedMemorySize, GEMM_SMEM);
    dim3 blk(256);

    // q/k projections -> fp16 (bias per column)
    {
        dim3 g(DD / BN, NC_ / BM);
        gemm_h<<<g, blk, GEMM_SMEM>>>(XH[0], WH[0], Bv[0], PH[0], NC_, DD, DD, 1, 1);
        gemm_h<<<g, blk, GEMM_SMEM>>>(XH[1], WH[1], Bv[1], PH[1], NC_, DD, DD, 1, 1);
        gemm_h<<<g, blk, GEMM_SMEM>>>(XH[3], WH[3], Bv[3], PH[3], NP_, DD, DD, 1, 1);
        gemm_h<<<g, blk, GEMM_SMEM>>>(XH[4], WH[4], Bv[4], PH[4], NP_, DD, DD, 1, 1);
    }
    // v projections TRANSPOSED -> fp16: vT = Wv @ X^T + b (bias per row)
    {
        dim3 g(NC_ / BN, DD / BM);
        gemm_h<<<g, blk, GEMM_SMEM>>>(WH[2], XH[2], Bv[2], PH[2], DD, NC_, DD, 2, 1);
        gemm_h<<<g, blk, GEMM_SMEM>>>(WH[5], XH[5], Bv[5], PH[5], DD, NP_, DD, 2, 1);
    }
    // scores -> fp32: S1 = qc @ kp^T, S2 = qp @ kc^T
    {
        dim3 g(NP_ / BN, NC_ / BM);
        gemm_h<<<g, blk, GEMM_SMEM>>>(PH[0], PH[4], nullptr, S1, NC_, NP_, DD, 0, 0);
        gemm_h<<<g, blk, GEMM_SMEM>>>(PH[3], PH[1], nullptr, S2, NP_, NC_, DD, 0, 0);
    }

    softmax4096<<<NC_, 256>>>(S1, P1);
    softmax4096<<<NP_, 256>>>(S2, P2);

    float* out = (float*)d_out;
    // comp = P1 @ vpT^T ; prot = P2 @ vcT^T  (fp32 outputs)
    {
        dim3 g(DD / BN, NC_ / BM);
        gemm_h<<<g, blk, GEMM_SMEM>>>(P1, PH[5], nullptr, out, NC_, DD, NP_, 0, 0);
        gemm_h<<<g, blk, GEMM_SMEM>>>(P2, PH[2], nullptr, out + (size_t)NC_ * DD, NP_, DD, NC_, 0, 0);
    }
}